// round 1
// baseline (speedup 1.0000x reference)
#include <cuda_runtime.h>

// Problem dims (fixed by the reference setup)
#define NB 4      // batch
#define NQ 16     // queries used (of 20)
#define NQP 20    // queries stored in btn_dec
#define NT 8      // t
#define NH 16     // h
#define NW 16     // w
#define ND 512    // d = G*C
#define NG 8      // heads
#define NC 64     // channels per head
#define NF 512    // btn_features

// 4 MB scratch for scores[b,q,t,h,w,g]
__device__ float g_scores[NB * NQ * NT * NH * NW * NG];

// ---------------------------------------------------------------------------
// Kernel 1: scores[b,q,t,hw,g] = sum_c dec[b,q,t,g,c] * enc[b,t,h,w,g,c]
// One thread per (b,t,h,w,g); each thread accumulates all 16 q in registers,
// so each enc element is loaded from DRAM exactly once (16.8 MB total).
// dec working set per block is ~32 KB -> L1 resident.
// ---------------------------------------------------------------------------
__global__ void __launch_bounds__(128) scores_kernel(
    const float* __restrict__ dec,   // (NB, NQP, NT, ND)
    const float* __restrict__ enc)   // (NB, NT, NH, NW, ND)
{
    int tid  = blockIdx.x * blockDim.x + threadIdx.x;   // 65536 threads
    int g    = tid & 7;
    int slab = tid >> 3;                                // (b,t,h,w): 8192 slabs
    if (slab >= NB * NT * NH * NW) return;

    int w = slab & 15;
    int h = (slab >> 4) & 15;
    int t = (slab >> 8) & 7;
    int b = slab >> 11;

    const float4* enc4 = reinterpret_cast<const float4*>(
        enc + (size_t)slab * ND + g * NC);
    const float* decb = dec + ((size_t)(b * NQP) * NT + t) * ND + g * NC;

    float4 acc[NQ];
#pragma unroll
    for (int q = 0; q < NQ; q++) acc[q] = make_float4(0.f, 0.f, 0.f, 0.f);

#pragma unroll
    for (int c4 = 0; c4 < NC / 4; c4++) {
        float4 e = enc4[c4];
#pragma unroll
        for (int q = 0; q < NQ; q++) {
            float4 dv = *reinterpret_cast<const float4*>(
                decb + (size_t)q * NT * ND + c4 * 4);
            acc[q].x = fmaf(e.x, dv.x, acc[q].x);
            acc[q].y = fmaf(e.y, dv.y, acc[q].y);
            acc[q].z = fmaf(e.z, dv.z, acc[q].z);
            acc[q].w = fmaf(e.w, dv.w, acc[q].w);
        }
    }

    int hw = h * 16 + w;
#pragma unroll
    for (int q = 0; q < NQ; q++) {
        float s = (acc[q].x + acc[q].y) + (acc[q].z + acc[q].w);
        // scores index: (((b*NQ+q)*NT + t)*(NH*NW) + hw)*NG + g
        // Within a warp (4 consecutive w, 8 g) this is 32 contiguous floats.
        g_scores[((((size_t)(b * NQ + q) * NT + t) * (NH * NW)) + hw) * NG + g] = s;
    }
}

// ---------------------------------------------------------------------------
// Kernel 2: out[row, f] = relu(sum_g scores[row, g] * W[g, f] + bias[f])
// row = (b,q,t,h,w), 131072 rows x 512 f. One thread per float4 of output.
// Scores are a warp-uniform broadcast load; W/bias hit L1. Pure stream write.
// ---------------------------------------------------------------------------
__global__ void __launch_bounds__(256) proj_kernel(
    const float* __restrict__ Wm,     // (NG, NF)
    const float* __restrict__ bias,   // (NF,)
    float* __restrict__ out)          // (rows, NF)
{
    int tid = blockIdx.x * blockDim.x + threadIdx.x;   // 16,777,216 threads
    int f4  = tid & 127;          // float4 index within the 512-wide row
    size_t row = (size_t)(tid >> 7);

    const float4* s4 = reinterpret_cast<const float4*>(g_scores + row * NG);
    float4 sA = s4[0];
    float4 sB = s4[1];

    const float4* W4 = reinterpret_cast<const float4*>(Wm);
    float4 acc = reinterpret_cast<const float4*>(bias)[f4];

    float4 wv;
    wv = W4[0 * 128 + f4];
    acc.x = fmaf(sA.x, wv.x, acc.x); acc.y = fmaf(sA.x, wv.y, acc.y);
    acc.z = fmaf(sA.x, wv.z, acc.z); acc.w = fmaf(sA.x, wv.w, acc.w);
    wv = W4[1 * 128 + f4];
    acc.x = fmaf(sA.y, wv.x, acc.x); acc.y = fmaf(sA.y, wv.y, acc.y);
    acc.z = fmaf(sA.y, wv.z, acc.z); acc.w = fmaf(sA.y, wv.w, acc.w);
    wv = W4[2 * 128 + f4];
    acc.x = fmaf(sA.z, wv.x, acc.x); acc.y = fmaf(sA.z, wv.y, acc.y);
    acc.z = fmaf(sA.z, wv.z, acc.z); acc.w = fmaf(sA.z, wv.w, acc.w);
    wv = W4[3 * 128 + f4];
    acc.x = fmaf(sA.w, wv.x, acc.x); acc.y = fmaf(sA.w, wv.y, acc.y);
    acc.z = fmaf(sA.w, wv.z, acc.z); acc.w = fmaf(sA.w, wv.w, acc.w);
    wv = W4[4 * 128 + f4];
    acc.x = fmaf(sB.x, wv.x, acc.x); acc.y = fmaf(sB.x, wv.y, acc.y);
    acc.z = fmaf(sB.x, wv.z, acc.z); acc.w = fmaf(sB.x, wv.w, acc.w);
    wv = W4[5 * 128 + f4];
    acc.x = fmaf(sB.y, wv.x, acc.x); acc.y = fmaf(sB.y, wv.y, acc.y);
    acc.z = fmaf(sB.y, wv.z, acc.z); acc.w = fmaf(sB.y, wv.w, acc.w);
    wv = W4[6 * 128 + f4];
    acc.x = fmaf(sB.z, wv.x, acc.x); acc.y = fmaf(sB.z, wv.y, acc.y);
    acc.z = fmaf(sB.z, wv.z, acc.z); acc.w = fmaf(sB.z, wv.w, acc.w);
    wv = W4[7 * 128 + f4];
    acc.x = fmaf(sB.w, wv.x, acc.x); acc.y = fmaf(sB.w, wv.y, acc.y);
    acc.z = fmaf(sB.w, wv.z, acc.z); acc.w = fmaf(sB.w, wv.w, acc.w);

    acc.x = fmaxf(acc.x, 0.f);
    acc.y = fmaxf(acc.y, 0.f);
    acc.z = fmaxf(acc.z, 0.f);
    acc.w = fmaxf(acc.w, 0.f);

    reinterpret_cast<float4*>(out)[tid] = acc;
}

extern "C" void kernel_launch(void* const* d_in, const int* in_sizes, int n_in,
                              void* d_out, int out_size)
{
    const float* dec  = (const float*)d_in[0];  // (4,20,8,512)
    const float* enc  = (const float*)d_in[1];  // (4,8,16,16,512)
    const float* Wm   = (const float*)d_in[2];  // (8,512)
    const float* bias = (const float*)d_in[3];  // (512,)
    float* out = (float*)d_out;                 // (4,16,8,16,16,512)

    // Kernel 1: 65536 threads (8192 slabs x 8 g)
    scores_kernel<<<512, 128>>>(dec, enc);

    // Kernel 2: 16,777,216 threads (131072 rows x 128 float4)
    proj_kernel<<<65536, 256>>>(Wm, bias, out);
}

// round 2
// speedup vs baseline: 1.5114x; 1.5114x over previous
#include <cuda_runtime.h>

// Problem dims (fixed by the reference setup)
#define NB 4      // batch
#define NQ 16     // queries used (of 20)
#define NQP 20    // queries stored in btn_dec
#define NT 8      // t
#define NHW 256   // h*w
#define HWT 16    // hw positions per block tile
#define ND 512    // d = G*C
#define NG 8      // heads
#define NC 64     // channels per head
#define NF 512    // btn_features

// packed f32x2 helpers (sm_103a)
__device__ __forceinline__ unsigned long long pack2(float lo, float hi) {
    unsigned long long r;
    asm("mov.b64 %0, {%1, %2};" : "=l"(r) : "f"(lo), "f"(hi));
    return r;
}
__device__ __forceinline__ void ffma2(unsigned long long& d,
                                      unsigned long long a,
                                      unsigned long long b) {
    asm("fma.rn.f32x2 %0, %1, %2, %0;" : "+l"(d) : "l"(a), "l"(b));
}
__device__ __forceinline__ void unpack2(unsigned long long v, float& lo, float& hi) {
    asm("mov.b64 {%0, %1}, %2;" : "=f"(lo), "=f"(hi) : "l"(v));
}

// ---------------------------------------------------------------------------
// Fused kernel.
// Grid: 512 blocks = (b:4) x (t:8) x (hw-tile:16), 256 threads.
//
// Phase A: scores[q:16][hw:16][g:8] -> 8KB smem.
//   thread = (qh:2, hw:16, g:8); 8 q-accumulators (float4 over c), enc/dec
//   read from global (tiles are L1/L2 resident; enc element read twice, once
//   per qh; dec tile shared by 16 blocks via L2).
// Phase B: out[q][hw][f] = relu(bias[f] + sum_g scores*W[g][f]).
//   thread = (rowgroup:2, f4:128); W(8 float4) + bias held in REGISTERS,
//   loop over 256 rows; per row: 2 broadcast smem loads, 16 FFMA2, 1 STG.128.
// ---------------------------------------------------------------------------
__global__ void __launch_bounds__(256) heatmap_fused_kernel(
    const float* __restrict__ dec,   // (4, 20, 8, 512)
    const float* __restrict__ enc,   // (4, 8, 16, 16, 512)
    const float* __restrict__ Wm,    // (8, 512)
    const float* __restrict__ bias,  // (512,)
    float* __restrict__ out)         // (4, 16, 8, 256, 512)
{
    __shared__ float scores_s[NQ * HWT * NG];   // 8 KB, [q][hw][g]

    const int tid = threadIdx.x;
    const int bid = blockIdx.x;
    const int hwt = bid & 15;          // hw tile
    const int t   = (bid >> 4) & 7;
    const int b   = bid >> 7;

    // ---------------- Phase A: scores ----------------
    {
        const int g   = tid & 7;
        const int hwl = (tid >> 3) & 15;
        const int qh  = tid >> 7;            // 0 or 1 (q = qh*8 + qi)

        const float4* enc4 = reinterpret_cast<const float4*>(
            enc + ((size_t)((b * NT + t) * NHW + hwt * HWT + hwl)) * ND + g * NC);
        const float4* dec4 = reinterpret_cast<const float4*>(
            dec + ((size_t)((b * NQP + qh * 8) * NT + t)) * ND + g * NC);
        // q stride in float4 units: NT*ND/4 = 1024

        float4 acc[8];
#pragma unroll
        for (int q = 0; q < 8; q++) acc[q] = make_float4(0.f, 0.f, 0.f, 0.f);

#pragma unroll
        for (int c4 = 0; c4 < NC / 4; c4++) {
            float4 e = enc4[c4];
#pragma unroll
            for (int q = 0; q < 8; q++) {
                float4 dv = dec4[q * 1024 + c4];
                acc[q].x = fmaf(e.x, dv.x, acc[q].x);
                acc[q].y = fmaf(e.y, dv.y, acc[q].y);
                acc[q].z = fmaf(e.z, dv.z, acc[q].z);
                acc[q].w = fmaf(e.w, dv.w, acc[q].w);
            }
        }
#pragma unroll
        for (int q = 0; q < 8; q++) {
            float s = (acc[q].x + acc[q].y) + (acc[q].z + acc[q].w);
            scores_s[(qh * 8 + q) * (HWT * NG) + hwl * NG + g] = s;
        }
    }
    __syncthreads();

    // ---------------- Phase B: projection + relu, stream out ----------------
    {
        const int f4 = tid & 127;        // float4 column 0..127
        const int rg = tid >> 7;         // row group 0/1

        // W[g][f4] and bias[f4] into registers as f32x2 pairs
        const float4* W4 = reinterpret_cast<const float4*>(Wm);
        unsigned long long wreg[NG][2];
#pragma unroll
        for (int g = 0; g < NG; g++) {
            float4 wv = W4[g * 128 + f4];
            wreg[g][0] = pack2(wv.x, wv.y);
            wreg[g][1] = pack2(wv.z, wv.w);
        }
        float4 bv = reinterpret_cast<const float4*>(bias)[f4];
        const unsigned long long b0 = pack2(bv.x, bv.y);
        const unsigned long long b1 = pack2(bv.z, bv.w);

        // out float4 base for this block: (((b*16+q)*8+t)*256 + hwt*16+hwl)*512/4
        float4* out4 = reinterpret_cast<float4*>(out);
        const size_t base4 =
            ((size_t)(b * NQ * NT + t) * NHW + hwt * HWT) * (NF / 4) + f4;
        // q stride (float4): 8*256*512/4 = 262144 ; hw stride: 512/4 = 128

        const float4* s4 = reinterpret_cast<const float4*>(scores_s);

#pragma unroll 4
        for (int r = rg; r < NQ * HWT; r += 2) {
            const int q   = r >> 4;
            const int hwl = r & 15;

            float4 sA = s4[r * 2 + 0];   // scores[r][0..3]
            float4 sB = s4[r * 2 + 1];   // scores[r][4..7]

            unsigned long long a0 = b0, a1 = b1;
            unsigned long long sp;
            sp = pack2(sA.x, sA.x); ffma2(a0, sp, wreg[0][0]); ffma2(a1, sp, wreg[0][1]);
            sp = pack2(sA.y, sA.y); ffma2(a0, sp, wreg[1][0]); ffma2(a1, sp, wreg[1][1]);
            sp = pack2(sA.z, sA.z); ffma2(a0, sp, wreg[2][0]); ffma2(a1, sp, wreg[2][1]);
            sp = pack2(sA.w, sA.w); ffma2(a0, sp, wreg[3][0]); ffma2(a1, sp, wreg[3][1]);
            sp = pack2(sB.x, sB.x); ffma2(a0, sp, wreg[4][0]); ffma2(a1, sp, wreg[4][1]);
            sp = pack2(sB.y, sB.y); ffma2(a0, sp, wreg[5][0]); ffma2(a1, sp, wreg[5][1]);
            sp = pack2(sB.z, sB.z); ffma2(a0, sp, wreg[6][0]); ffma2(a1, sp, wreg[6][1]);
            sp = pack2(sB.w, sB.w); ffma2(a0, sp, wreg[7][0]); ffma2(a1, sp, wreg[7][1]);

            float4 res;
            unpack2(a0, res.x, res.y);
            unpack2(a1, res.z, res.w);
            res.x = fmaxf(res.x, 0.f);
            res.y = fmaxf(res.y, 0.f);
            res.z = fmaxf(res.z, 0.f);
            res.w = fmaxf(res.w, 0.f);

            out4[base4 + (size_t)q * 262144 + hwl * 128] = res;
        }
    }
}

extern "C" void kernel_launch(void* const* d_in, const int* in_sizes, int n_in,
                              void* d_out, int out_size)
{
    const float* dec  = (const float*)d_in[0];  // (4,20,8,512)
    const float* enc  = (const float*)d_in[1];  // (4,8,16,16,512)
    const float* Wm   = (const float*)d_in[2];  // (8,512)
    const float* bias = (const float*)d_in[3];  // (512,)
    float* out = (float*)d_out;                 // (4,16,8,16,16,512)

    heatmap_fused_kernel<<<NB * NT * (NHW / HWT), 256>>>(dec, enc, Wm, bias, out);
}

// round 3
// speedup vs baseline: 1.5157x; 1.0028x over previous
#include <cuda_runtime.h>

// Problem dims (fixed by the reference setup)
#define NB 4      // batch
#define NQ 16     // queries used (of 20)
#define NQP 20    // queries stored in btn_dec
#define NT 8      // t
#define NHW 256   // h*w
#define HWT 8     // hw positions per block tile
#define ND 512    // d = G*C
#define NG 8      // heads
#define NC 64     // channels per head
#define NF 512    // btn_features

// packed f32x2 helpers (sm_103a)
__device__ __forceinline__ unsigned long long pack2(float lo, float hi) {
    unsigned long long r;
    asm("mov.b64 %0, {%1, %2};" : "=l"(r) : "f"(lo), "f"(hi));
    return r;
}
__device__ __forceinline__ void ffma2(unsigned long long& d,
                                      unsigned long long a,
                                      unsigned long long b) {
    asm("fma.rn.f32x2 %0, %1, %2, %0;" : "+l"(d) : "l"(a), "l"(b));
}
__device__ __forceinline__ void unpack2(unsigned long long v, float& lo, float& hi) {
    asm("mov.b64 {%0, %1}, %2;" : "=f"(lo), "=f"(hi) : "l"(v));
}

// ---------------------------------------------------------------------------
// Fused kernel, residency-tuned.
// Grid: 1024 blocks = (b:4) x (t:8) x (hw-tile:32), 128 threads.
//   -> 8 blocks/SM (regs capped at 64), single wave on 148 SMs.
//
// Phase A: scores[q:16][hw:8][g:8] -> 4KB smem.
//   thread = (qh:2, hw:8, g:8); two passes of 4 q-accumulators to keep
//   live registers low; enc float4s re-hit L1 on pass 2.
// Phase B: thread = f4 (0..127); W(8 float4)+bias in registers, loop over
//   128 rows; per row: 2 broadcast smem loads, 16 FFMA2, 1 streaming STG.128.
// ---------------------------------------------------------------------------
__global__ void __launch_bounds__(128, 8) heatmap_fused_kernel(
    const float* __restrict__ dec,   // (4, 20, 8, 512)
    const float* __restrict__ enc,   // (4, 8, 16, 16, 512)
    const float* __restrict__ Wm,    // (8, 512)
    const float* __restrict__ bias,  // (512,)
    float* __restrict__ out)         // (4, 16, 8, 256, 512)
{
    __shared__ float scores_s[NQ * HWT * NG];   // 4 KB, [q][hw][g]

    const int tid = threadIdx.x;
    const int bid = blockIdx.x;
    const int hwt = bid & 31;          // hw tile (8 positions)
    const int t   = (bid >> 5) & 7;
    const int b   = bid >> 8;

    // ---------------- Phase A: scores ----------------
    {
        const int g   = tid & 7;
        const int hwl = (tid >> 3) & 7;
        const int qh  = tid >> 6;            // 0 or 1  (q = qh*8 + pass*4 + qi)

        const float4* enc4 = reinterpret_cast<const float4*>(
            enc + ((size_t)((b * NT + t) * NHW + hwt * HWT + hwl)) * ND + g * NC);

#pragma unroll
        for (int pass = 0; pass < 2; pass++) {
            const float4* dec4 = reinterpret_cast<const float4*>(
                dec + ((size_t)((b * NQP + qh * 8 + pass * 4) * NT + t)) * ND + g * NC);
            // q stride in float4 units: NT*ND/4 = 1024

            float4 acc[4];
#pragma unroll
            for (int q = 0; q < 4; q++) acc[q] = make_float4(0.f, 0.f, 0.f, 0.f);

#pragma unroll
            for (int c4 = 0; c4 < NC / 4; c4++) {
                float4 e = enc4[c4];
#pragma unroll
                for (int q = 0; q < 4; q++) {
                    float4 dv = dec4[q * 1024 + c4];
                    acc[q].x = fmaf(e.x, dv.x, acc[q].x);
                    acc[q].y = fmaf(e.y, dv.y, acc[q].y);
                    acc[q].z = fmaf(e.z, dv.z, acc[q].z);
                    acc[q].w = fmaf(e.w, dv.w, acc[q].w);
                }
            }
#pragma unroll
            for (int q = 0; q < 4; q++) {
                float s = (acc[q].x + acc[q].y) + (acc[q].z + acc[q].w);
                scores_s[(qh * 8 + pass * 4 + q) * (HWT * NG) + hwl * NG + g] = s;
            }
        }
    }
    __syncthreads();

    // ---------------- Phase B: projection + relu, stream out ----------------
    {
        const int f4 = tid;              // float4 column 0..127

        // W[g][f4] and bias[f4] into registers as f32x2 pairs
        const float4* W4 = reinterpret_cast<const float4*>(Wm);
        unsigned long long wreg[NG][2];
#pragma unroll
        for (int g = 0; g < NG; g++) {
            float4 wv = W4[g * 128 + f4];
            wreg[g][0] = pack2(wv.x, wv.y);
            wreg[g][1] = pack2(wv.z, wv.w);
        }
        float4 bv = reinterpret_cast<const float4*>(bias)[f4];
        const unsigned long long bb0 = pack2(bv.x, bv.y);
        const unsigned long long bb1 = pack2(bv.z, bv.w);

        float4* out4 = reinterpret_cast<float4*>(out);
        // out float4 index: (((b*16+q)*8+t)*256 + hwt*8+hwl)*128 + f4
        const size_t base4 =
            ((size_t)(b * NQ * NT + t) * NHW + hwt * HWT) * (NF / 4) + f4;
        // q stride (float4): 8*256*128 = 262144 ; hwl stride: 128

        const float4* s4 = reinterpret_cast<const float4*>(scores_s);

#pragma unroll 4
        for (int r = 0; r < NQ * HWT; r++) {
            const int q   = r >> 3;
            const int hwl = r & 7;

            float4 sA = s4[r * 2 + 0];   // scores[r][0..3]
            float4 sB = s4[r * 2 + 1];   // scores[r][4..7]

            unsigned long long a0 = bb0, a1 = bb1;
            unsigned long long sp;
            sp = pack2(sA.x, sA.x); ffma2(a0, sp, wreg[0][0]); ffma2(a1, sp, wreg[0][1]);
            sp = pack2(sA.y, sA.y); ffma2(a0, sp, wreg[1][0]); ffma2(a1, sp, wreg[1][1]);
            sp = pack2(sA.z, sA.z); ffma2(a0, sp, wreg[2][0]); ffma2(a1, sp, wreg[2][1]);
            sp = pack2(sA.w, sA.w); ffma2(a0, sp, wreg[3][0]); ffma2(a1, sp, wreg[3][1]);
            sp = pack2(sB.x, sB.x); ffma2(a0, sp, wreg[4][0]); ffma2(a1, sp, wreg[4][1]);
            sp = pack2(sB.y, sB.y); ffma2(a0, sp, wreg[5][0]); ffma2(a1, sp, wreg[5][1]);
            sp = pack2(sB.z, sB.z); ffma2(a0, sp, wreg[6][0]); ffma2(a1, sp, wreg[6][1]);
            sp = pack2(sB.w, sB.w); ffma2(a0, sp, wreg[7][0]); ffma2(a1, sp, wreg[7][1]);

            float4 res;
            unpack2(a0, res.x, res.y);
            unpack2(a1, res.z, res.w);
            res.x = fmaxf(res.x, 0.f);
            res.y = fmaxf(res.y, 0.f);
            res.z = fmaxf(res.z, 0.f);
            res.w = fmaxf(res.w, 0.f);

            __stcs(&out4[base4 + (size_t)q * 262144 + hwl * 128], res);
        }
    }
}

extern "C" void kernel_launch(void* const* d_in, const int* in_sizes, int n_in,
                              void* d_out, int out_size)
{
    const float* dec  = (const float*)d_in[0];  // (4,20,8,512)
    const float* enc  = (const float*)d_in[1];  // (4,8,16,16,512)
    const float* Wm   = (const float*)d_in[2];  // (8,512)
    const float* bias = (const float*)d_in[3];  // (512,)
    float* out = (float*)d_out;                 // (4,16,8,16,16,512)

    heatmap_fused_kernel<<<NB * NT * (NHW / HWT), 128>>>(dec, enc, Wm, bias, out);
}

// round 4
// speedup vs baseline: 2.1869x; 1.4429x over previous
#include <cuda_runtime.h>

// Problem dims (fixed by the reference setup)
#define NB 4      // batch
#define NQ 16     // queries used (of 20)
#define NQP 20    // queries stored in btn_dec
#define NT 8      // t
#define NHW 256   // h*w
#define ND 512    // d = G*C
#define NG 8      // heads
#define NC 64     // channels per head
#define NF 512    // btn_features
#define NROWS (NB * NQ * NT * NHW)   // 131072 output rows

// Scratch: scores duplicated as (s,s) pairs: [row][2*g + {0,1}] -> 16 floats/row, 8 MB
__device__ float g_scores2[NROWS * 2 * NG];

__device__ __forceinline__ float dot4(float4 a, float4 b) {
    return fmaf(a.x, b.x, fmaf(a.y, b.y, fmaf(a.z, b.z, a.w * b.w)));
}

__device__ __forceinline__ void ffma2(unsigned long long& d,
                                      unsigned long long a,
                                      unsigned long long b) {
    asm("fma.rn.f32x2 %0, %1, %2, %0;" : "+l"(d) : "l"(a), "l"(b));
}

// ---------------------------------------------------------------------------
// K1: one warp per (b,t,hw). Warp loads the full 512-float enc row with 4
// CONTIGUOUS LDG.128 (full 128B-line utilization), then for each q loads the
// dec row the same way (L1/L2-hot: shared by all 256 hw warps of a (b,t)),
// computes per-lane dot4 partials and reduces each 16-lane half with
// shfl_xor. Writes scores duplicated as (s,s) pairs for K2's FFMA2.
// ---------------------------------------------------------------------------
__global__ void __launch_bounds__(256) scores_kernel(
    const float* __restrict__ dec,   // (4, 20, 8, 512)
    const float* __restrict__ enc)   // (4, 8, 256, 512)
{
    const int lane = threadIdx.x & 31;
    const int slab = (blockIdx.x * blockDim.x + threadIdx.x) >> 5;  // 8192
    const int hw = slab & 255;
    const int t  = (slab >> 8) & 7;
    const int b  = slab >> 11;

    const float4* enc4 = reinterpret_cast<const float4*>(enc) + (size_t)slab * 128;
    float4 e0 = enc4[lane];
    float4 e1 = enc4[lane + 32];
    float4 e2 = enc4[lane + 64];
    float4 e3 = enc4[lane + 96];

    const int half  = lane >> 4;       // which 16-lane half (head parity)
    const int lh    = lane & 15;
    const int j_sel = lh >> 1;         // which partial this lane writes
    const int dup   = lane & 1;        // which element of the (s,s) pair
    const bool active = lh < 8;
    // write offset within the 16-float row: 2*head + dup, head = 2*j_sel + half
    const int woff = 4 * j_sel + 2 * half + dup;

    // scores2 row for q=0: (((b*16+0)*8+t)*256+hw) * 16 floats
    float* srow = g_scores2 + (((size_t)(b * NQ) * NT + t) * NHW + hw) * 16 + woff;
    // q stride in floats: 8*256*16 = 32768

#pragma unroll
    for (int q = 0; q < NQ; q++) {
        const float4* dec4 = reinterpret_cast<const float4*>(dec)
                           + ((size_t)((b * NQP + q) * NT + t)) * 128;
        float p0 = dot4(e0, dec4[lane]);
        float p1 = dot4(e1, dec4[lane + 32]);
        float p2 = dot4(e2, dec4[lane + 64]);
        float p3 = dot4(e3, dec4[lane + 96]);
        // reduce each partial across its 16-lane half (heads 2j+half)
#pragma unroll
        for (int m = 1; m <= 8; m <<= 1) {
            p0 += __shfl_xor_sync(0xffffffffu, p0, m);
            p1 += __shfl_xor_sync(0xffffffffu, p1, m);
            p2 += __shfl_xor_sync(0xffffffffu, p2, m);
            p3 += __shfl_xor_sync(0xffffffffu, p3, m);
        }
        float s = (j_sel == 0) ? p0 : (j_sel == 1) ? p1 : (j_sel == 2) ? p2 : p3;
        if (active) srow[(size_t)q * 32768] = s;
    }
}

// ---------------------------------------------------------------------------
// K2: thread = fixed f4 column (0..127). W (8 packed f32x2 pairs) + bias in
// registers. Loops 64 consecutive rows; per row: 4 warp-uniform broadcast
// LDG.128 of pre-duplicated scores (zero pack MOVs), 16 FFMA2, 1 coalesced
// streaming STG.128. Pure output stream -> DRAM-bound by design.
// ---------------------------------------------------------------------------
#define RPB 64   // rows per block

__global__ void __launch_bounds__(128) proj_kernel(
    const float* __restrict__ Wm,     // (8, 512)
    const float* __restrict__ bias,   // (512,)
    float* __restrict__ out)          // (131072, 512)
{
    const int f4 = threadIdx.x;
    const size_t row0 = (size_t)blockIdx.x * RPB;

    // W[g] pair columns (4f4, 4f4+1) and (4f4+2, 4f4+3) packed in registers
    const unsigned long long* W2 = reinterpret_cast<const unsigned long long*>(Wm);
    unsigned long long wreg[NG][2];
#pragma unroll
    for (int g = 0; g < NG; g++) {
        wreg[g][0] = W2[g * 256 + f4 * 2];
        wreg[g][1] = W2[g * 256 + f4 * 2 + 1];
    }
    const unsigned long long* B2 = reinterpret_cast<const unsigned long long*>(bias);
    const unsigned long long bb0 = B2[f4 * 2];
    const unsigned long long bb1 = B2[f4 * 2 + 1];

    const ulonglong2* sc = reinterpret_cast<const ulonglong2*>(g_scores2) + row0 * 4;
    float4* out4 = reinterpret_cast<float4*>(out) + row0 * 128 + f4;

#pragma unroll 2
    for (int r = 0; r < RPB; r++) {
        ulonglong2 u01 = sc[r * 4 + 0];   // (s0,s0),(s1,s1)
        ulonglong2 u23 = sc[r * 4 + 1];
        ulonglong2 u45 = sc[r * 4 + 2];
        ulonglong2 u67 = sc[r * 4 + 3];

        unsigned long long a0 = bb0, a1 = bb1;
        ffma2(a0, u01.x, wreg[0][0]); ffma2(a1, u01.x, wreg[0][1]);
        ffma2(a0, u01.y, wreg[1][0]); ffma2(a1, u01.y, wreg[1][1]);
        ffma2(a0, u23.x, wreg[2][0]); ffma2(a1, u23.x, wreg[2][1]);
        ffma2(a0, u23.y, wreg[3][0]); ffma2(a1, u23.y, wreg[3][1]);
        ffma2(a0, u45.x, wreg[4][0]); ffma2(a1, u45.x, wreg[4][1]);
        ffma2(a0, u45.y, wreg[5][0]); ffma2(a1, u45.y, wreg[5][1]);
        ffma2(a0, u67.x, wreg[6][0]); ffma2(a1, u67.x, wreg[6][1]);
        ffma2(a0, u67.y, wreg[7][0]); ffma2(a1, u67.y, wreg[7][1]);

        float4 res;
        asm("mov.b64 {%0, %1}, %2;" : "=f"(res.x), "=f"(res.y) : "l"(a0));
        asm("mov.b64 {%0, %1}, %2;" : "=f"(res.z), "=f"(res.w) : "l"(a1));
        res.x = fmaxf(res.x, 0.f);
        res.y = fmaxf(res.y, 0.f);
        res.z = fmaxf(res.z, 0.f);
        res.w = fmaxf(res.w, 0.f);

        __stcs(&out4[r * 128], res);
    }
}

extern "C" void kernel_launch(void* const* d_in, const int* in_sizes, int n_in,
                              void* d_out, int out_size)
{
    const float* dec  = (const float*)d_in[0];  // (4,20,8,512)
    const float* enc  = (const float*)d_in[1];  // (4,8,16,16,512)
    const float* Wm   = (const float*)d_in[2];  // (8,512)
    const float* bias = (const float*)d_in[3];  // (512,)
    float* out = (float*)d_out;                 // (4,16,8,16,16,512)

    // K1: 8192 warps (one per (b,t,hw)) = 1024 blocks x 256 threads
    scores_kernel<<<1024, 256>>>(dec, enc);

    // K2: 131072 rows / 64 rows-per-block = 2048 blocks x 128 threads
    proj_kernel<<<NROWS / RPB, 128>>>(Wm, bias, out);
}

// round 5
// speedup vs baseline: 2.5144x; 1.1497x over previous
#include <cuda_runtime.h>

// Problem dims (fixed by the reference setup)
#define NB 4      // batch
#define NQ 16     // queries used (of 20)
#define NQP 20    // queries stored in btn_dec
#define NT 8      // t
#define NHW 256   // h*w
#define ND 512    // d = G*C
#define NG 8      // heads
#define NC 64     // channels per head
#define NF 512    // btn_features
#define NROWS (NB * NQ * NT * NHW)   // 131072 output rows

// Scratch: scores duplicated as (s,s) pairs: [row][2*g + {0,1}] -> 16 floats/row, 8 MB
__device__ float g_scores2[NROWS * 2 * NG];

__device__ __forceinline__ float dot4(float4 a, float4 b) {
    return fmaf(a.x, b.x, fmaf(a.y, b.y, fmaf(a.z, b.z, a.w * b.w)));
}

__device__ __forceinline__ void ffma2(unsigned long long& d,
                                      unsigned long long a,
                                      unsigned long long b) {
    asm("fma.rn.f32x2 %0, %1, %2, %0;" : "+l"(d) : "l"(a), "l"(b));
}

// ---------------------------------------------------------------------------
// K1: one warp per (b,t,hw). Warp loads the full 512-float enc row with 4
// CONTIGUOUS LDG.128, dec rows likewise (L1/L2-hot), per-lane dot4 partials,
// shfl_xor reduction per 16-lane half. Writes scores pre-duplicated as (s,s)
// pairs so K2's FFMA2 needs zero packing. (~0.5us, unchanged from R4.)
// ---------------------------------------------------------------------------
__global__ void __launch_bounds__(256) scores_kernel(
    const float* __restrict__ dec,   // (4, 20, 8, 512)
    const float* __restrict__ enc)   // (4, 8, 256, 512)
{
    const int lane = threadIdx.x & 31;
    const int slab = (blockIdx.x * blockDim.x + threadIdx.x) >> 5;  // 8192
    const int hw = slab & 255;
    const int t  = (slab >> 8) & 7;
    const int b  = slab >> 11;

    const float4* enc4 = reinterpret_cast<const float4*>(enc) + (size_t)slab * 128;
    float4 e0 = enc4[lane];
    float4 e1 = enc4[lane + 32];
    float4 e2 = enc4[lane + 64];
    float4 e3 = enc4[lane + 96];

    const int half  = lane >> 4;       // which 16-lane half (head parity)
    const int lh    = lane & 15;
    const int j_sel = lh >> 1;         // which partial this lane writes
    const int dup   = lane & 1;        // which element of the (s,s) pair
    const bool active = lh < 8;
    const int woff = 4 * j_sel + 2 * half + dup;

    float* srow = g_scores2 + (((size_t)(b * NQ) * NT + t) * NHW + hw) * 16 + woff;
    // q stride in floats: 8*256*16 = 32768

#pragma unroll
    for (int q = 0; q < NQ; q++) {
        const float4* dec4 = reinterpret_cast<const float4*>(dec)
                           + ((size_t)((b * NQP + q) * NT + t)) * 128;
        float p0 = dot4(e0, dec4[lane]);
        float p1 = dot4(e1, dec4[lane + 32]);
        float p2 = dot4(e2, dec4[lane + 64]);
        float p3 = dot4(e3, dec4[lane + 96]);
#pragma unroll
        for (int m = 1; m <= 8; m <<= 1) {
            p0 += __shfl_xor_sync(0xffffffffu, p0, m);
            p1 += __shfl_xor_sync(0xffffffffu, p1, m);
            p2 += __shfl_xor_sync(0xffffffffu, p2, m);
            p3 += __shfl_xor_sync(0xffffffffu, p3, m);
        }
        float s = (j_sel == 0) ? p0 : (j_sel == 1) ? p1 : (j_sel == 2) ? p2 : p3;
        if (active) srow[(size_t)q * 32768] = s;
    }
}

// ---------------------------------------------------------------------------
// K2: thread = fixed f4 column (0..127), RPB=64 rows per block.
// Prologue: bulk-load the block's 4KB of (pre-duplicated) scores into smem
// with one coalesced pass. Inner loop per row: 2 broadcast LDS.128 (29cyc,
// hidden), 16 FFMA2, 1 streaming STG.128 -- NO long-latency op between
// stores, so the store stream runs at pipe rate and DRAM saturates.
// ---------------------------------------------------------------------------
#define RPB 64   // rows per block

__global__ void __launch_bounds__(128, 8) proj_kernel(
    const float* __restrict__ Wm,     // (8, 512)
    const float* __restrict__ bias,   // (512,)
    float* __restrict__ out)          // (131072, 512)
{
    __shared__ float sc_s[RPB * 16];  // 4 KB

    const int f4 = threadIdx.x;
    const size_t row0 = (size_t)blockIdx.x * RPB;

    // Bulk-stage scores: 4KB = 256 float4, 128 threads x 2
    {
        const float4* gsc = reinterpret_cast<const float4*>(g_scores2 + row0 * 16);
        float4* ssc = reinterpret_cast<float4*>(sc_s);
        ssc[f4]       = gsc[f4];
        ssc[f4 + 128] = gsc[f4 + 128];
    }

    // W[g] pair columns and bias packed in registers
    const unsigned long long* W2 = reinterpret_cast<const unsigned long long*>(Wm);
    unsigned long long wreg[NG][2];
#pragma unroll
    for (int g = 0; g < NG; g++) {
        wreg[g][0] = W2[g * 256 + f4 * 2];
        wreg[g][1] = W2[g * 256 + f4 * 2 + 1];
    }
    const unsigned long long* B2 = reinterpret_cast<const unsigned long long*>(bias);
    const unsigned long long bb0 = B2[f4 * 2];
    const unsigned long long bb1 = B2[f4 * 2 + 1];

    __syncthreads();

    const ulonglong2* sc = reinterpret_cast<const ulonglong2*>(sc_s);
    float4* out4 = reinterpret_cast<float4*>(out) + row0 * 128 + f4;

#pragma unroll 4
    for (int r = 0; r < RPB; r++) {
        ulonglong2 u01 = sc[r * 4 + 0];   // (s0,s0),(s1,s1)
        ulonglong2 u23 = sc[r * 4 + 1];
        ulonglong2 u45 = sc[r * 4 + 2];
        ulonglong2 u67 = sc[r * 4 + 3];

        unsigned long long a0 = bb0, a1 = bb1;
        ffma2(a0, u01.x, wreg[0][0]); ffma2(a1, u01.x, wreg[0][1]);
        ffma2(a0, u01.y, wreg[1][0]); ffma2(a1, u01.y, wreg[1][1]);
        ffma2(a0, u23.x, wreg[2][0]); ffma2(a1, u23.x, wreg[2][1]);
        ffma2(a0, u23.y, wreg[3][0]); ffma2(a1, u23.y, wreg[3][1]);
        ffma2(a0, u45.x, wreg[4][0]); ffma2(a1, u45.x, wreg[4][1]);
        ffma2(a0, u45.y, wreg[5][0]); ffma2(a1, u45.y, wreg[5][1]);
        ffma2(a0, u67.x, wreg[6][0]); ffma2(a1, u67.x, wreg[6][1]);
        ffma2(a0, u67.y, wreg[7][0]); ffma2(a1, u67.y, wreg[7][1]);

        float4 res;
        asm("mov.b64 {%0, %1}, %2;" : "=f"(res.x), "=f"(res.y) : "l"(a0));
        asm("mov.b64 {%0, %1}, %2;" : "=f"(res.z), "=f"(res.w) : "l"(a1));
        res.x = fmaxf(res.x, 0.f);
        res.y = fmaxf(res.y, 0.f);
        res.z = fmaxf(res.z, 0.f);
        res.w = fmaxf(res.w, 0.f);

        __stcs(&out4[r * 128], res);
    }
}

extern "C" void kernel_launch(void* const* d_in, const int* in_sizes, int n_in,
                              void* d_out, int out_size)
{
    const float* dec  = (const float*)d_in[0];  // (4,20,8,512)
    const float* enc  = (const float*)d_in[1];  // (4,8,16,16,512)
    const float* Wm   = (const float*)d_in[2];  // (8,512)
    const float* bias = (const float*)d_in[3];  // (512,)
    float* out = (float*)d_out;                 // (4,16,8,16,16,512)

    // K1: 8192 warps (one per (b,t,hw)) = 1024 blocks x 256 threads
    scores_kernel<<<1024, 256>>>(dec, enc);

    // K2: 131072 rows / 64 rows-per-block = 2048 blocks x 128 threads
    proj_kernel<<<NROWS / RPB, 128>>>(Wm, bias, out);
}